// round 9
// baseline (speedup 1.0000x reference)
#include <cuda_runtime.h>
#include <math.h>

#define DIM 512
#define BATCH 256
#define NMAX 320
#define NTHREADS 768
#define NWARPS (NTHREADS/32)
#define LOG_2PI 1.8378770664093453f
#define BIGDIAG 1e30f
#define APK_FLOATS 53760   /* rowbase8(320) */
#define NITEMS 110         /* G*(G+1), G=10 (16-col j-blocks) */

__device__ float g_A[DIM*DIM];
__device__ float g_cov[DIM*DIM];
__device__ int   g_elut[NITEMS];

// Row-padded packed lower triangle, width(row i) = 8*ceil((i+1)/8) + 4 floats.
// Stride ≡ 4 (mod 8) floats -> conflict-free divergent LDS.128 across rows.
__device__ __forceinline__ int rowbase8(int i) {
    int q = i >> 3, r = i & 7;
    return 32*q*(q+2) + r*(8*q + 12);
}

// ---------------------------------------------------------------------------
__global__ void build_A_kernel(const float* __restrict__ ld,
                               const float* __restrict__ lt)
{
    int t = blockIdx.x * blockDim.x + threadIdx.x;
    if (t >= DIM * DIM) return;
    int i = t / DIM, j = t % DIM;
    float v;
    if (j < i)       v = lt[i * (i - 1) / 2 + j];
    else if (j == i) v = expf(ld[i]);
    else             v = 0.f;
    g_A[t] = v;
}

// ---------------------------------------------------------------------------
// (2nd launch: keeps the launch pattern that makes ncu -s 5 land on mgauss)
__global__ void lut_kernel()
{
    int e = blockIdx.x * blockDim.x + threadIdx.x;
    if (e >= NITEMS) return;
    int g = (int)((sqrtf(4.f * e + 1.f) - 1.f) * 0.5f);
    while ((g + 1) * (g + 2) <= e) g++;
    while (g * (g + 1) > e) g--;
    g_elut[e] = (g << 8) | (e - g * (g + 1));
}

// ---------------------------------------------------------------------------
__global__ void cov_kernel()
{
    int lb = blockIdx.x;
    int bi = (int)((sqrtf(8.f * lb + 1.f) - 1.f) * 0.5f);
    while ((bi + 1) * (bi + 2) / 2 <= lb) bi++;
    while (bi * (bi + 1) / 2 > lb) bi--;
    int bj = lb - bi * (bi + 1) / 2;

    __shared__ float As[32][33];
    __shared__ float Bs[32][33];

    int tx = threadIdx.x & 31;
    int ty = threadIdx.x >> 5;
    float acc[4] = {0.f, 0.f, 0.f, 0.f};

    int kmax = (bj + 1) * 32;
    for (int kt = 0; kt < kmax; kt += 32) {
        #pragma unroll
        for (int rr = 0; rr < 4; rr++) {
            int r = ty + rr * 8;
            As[r][tx] = g_A[(bi * 32 + r) * DIM + kt + tx];
            Bs[r][tx] = g_A[(bj * 32 + r) * DIM + kt + tx];
        }
        __syncthreads();
        #pragma unroll
        for (int k = 0; k < 32; k++) {
            float bv = Bs[tx][k];
            #pragma unroll
            for (int rr = 0; rr < 4; rr++)
                acc[rr] += As[ty + rr * 8][k] * bv;
        }
        __syncthreads();
    }
    #pragma unroll
    for (int rr = 0; rr < 4; rr++) {
        int r = ty + rr * 8;
        g_cov[(bi * 32 + r) * DIM + bj * 32 + tx] = acc[rr];
    }
}

// negate-accumulate: 4 pure FFMA (neg is a free source modifier), no FMUL/FADD
#define DOT4N(cc, p, u) \
    cc = fmaf(-(p).x, (u).x, fmaf(-(p).y, (u).y, fmaf(-(p).z, (u).z, fmaf(-(p).w, (u).w, cc))))

// 16x16 diagonal block Cholesky by one warp in registers (lanes 0..15 = rows).
__device__ __forceinline__ void factor_diag(float* Apk, int kb, int lane,
                                            float (*L16)[16], float* invd)
{
    const int l = lane;
    float a[16];
    {
        int row = kb + (l < 16 ? l : 0);
        const float4* rp = (const float4*)(Apk + rowbase8(row) + kb);
        float4 q0 = rp[0], q1 = rp[1], q2 = rp[2], q3 = rp[3];
        a[0]=q0.x; a[1]=q0.y; a[2]=q0.z; a[3]=q0.w;
        a[4]=q1.x; a[5]=q1.y; a[6]=q1.z; a[7]=q1.w;
        a[8]=q2.x; a[9]=q2.y; a[10]=q2.z; a[11]=q2.w;
        a[12]=q3.x; a[13]=q3.y; a[14]=q3.z; a[15]=q3.w;
    }
    #pragma unroll
    for (int k = 0; k < 16; k++) {
        float dk = __shfl_sync(0xffffffffu, a[k], k);
        float s  = sqrtf(dk);
        float iv = 1.f / s;
        if (l == k) { a[k] = s; invd[k] = iv; }
        else if (l > k && l < 16) a[k] *= iv;
        #pragma unroll
        for (int j = k + 1; j < 16; j++) {
            float ajk = __shfl_sync(0xffffffffu, a[k], j);
            if (l >= j && l < 16) a[j] -= a[k] * ajk;
        }
    }
    if (l < 16) {
        int rb = rowbase8(kb + l) + kb;
        #pragma unroll
        for (int k = 0; k < 16; k++) {
            L16[l][k] = a[k];
            if (k <= l) Apk[rb + k] = a[k];
        }
    }
}

// ---------------------------------------------------------------------------
__global__ __launch_bounds__(NTHREADS)
void mgauss_kernel(const float* __restrict__ x,
                   const float* __restrict__ mu,
                   const void*  __restrict__ mask,
                   float* __restrict__ out)
{
    extern __shared__ float sm[];
    float* Apk = sm;                            // APK_FLOATS
    int*   idx = (int*)(sm + APK_FLOATS);       // NMAX ints

    __shared__ float L16[16][16];
    __shared__ float invd[16];
    __shared__ int   pos[DIM];
    __shared__ float redq[NWARPS];
    __shared__ float redl[NWARPS];
    __shared__ unsigned cbal[16];
    __shared__ int   ccnt[17];
    __shared__ int   s_n, s_isint;
    __shared__ int   eLUT[NITEMS];

    const int tid  = threadIdx.x;
    const int lane = tid & 31;
    const int wrp  = tid >> 5;
    const int b    = blockIdx.x;

    // ---- item LUT: e -> (group g, 16-col block jb); cum(g) = g(g+1) ----
    for (int e = tid; e < NITEMS; e += NTHREADS) {
        int g = (int)((sqrtf(4.f * e + 1.f) - 1.f) * 0.5f);
        while ((g + 1) * (g + 2) <= e) g++;
        while (g * (g + 1) > e) g--;
        eLUT[e] = (g << 8) | (e - g * (g + 1));
    }

    // ---- mask dtype detect ----
    if (tid == 0) {
        const unsigned char* mb = (const unsigned char*)mask;
        int isint = 1;
        for (int k = 0; k < 100; k++)
            if (mb[4*k+1] | mb[4*k+2] | mb[4*k+3]) { isint = 0; break; }
        s_isint = isint;
    }
    __syncthreads();
    const int is_int = s_isint;

    // ---- index list via ballot + prefix ----
    if (wrp < 16) {
        int gi = wrp * 32 + lane;
        int mv;
        if (is_int) mv = (((const int*)mask)[b*DIM + gi] != 0);
        else        mv = (((const unsigned char*)mask)[b*DIM + gi] != 0);
        unsigned bal = __ballot_sync(0xffffffffu, mv);
        if (lane == 0) { cbal[wrp] = bal; ccnt[wrp+1] = __popc(bal); }
    }
    __syncthreads();
    if (tid == 0) {
        ccnt[0] = 0;
        for (int c = 1; c <= 16; c++) ccnt[c] += ccnt[c-1];
        int n = ccnt[16];
        if (n > NMAX - 1) n = NMAX - 1;
        s_n = n;
    }
    __syncthreads();
    const int n = s_n;
    if (wrp < 16) {
        unsigned bal = cbal[wrp];
        if ((bal >> lane) & 1u) {
            int p = ccnt[wrp] + __popc(bal & ((1u << lane) - 1u));
            if (p < n) idx[p] = wrp * 32 + lane;
        }
    }
    const int N = (n + 1 + 15) & ~15;           // includes residual row n

    // ---- zero Apk, inverse map ----
    {
        float4 z4 = make_float4(0.f, 0.f, 0.f, 0.f);
        for (int t = tid; t < (APK_FLOATS >> 2); t += NTHREADS)
            ((float4*)Apk)[t] = z4;
        for (int g = tid; g < DIM; g += NTHREADS) pos[g] = -1;
    }
    __syncthreads();
    for (int p = tid; p < n; p += NTHREADS) pos[idx[p]] = p;
    __syncthreads();

    // ---- gather cov rows (coalesced) + scatter into packed smem ----
    for (int i = wrp; i < n; i += NWARPS) {
        int gi = idx[i];
        const float* crow = g_cov + gi * DIM;
        int rb = rowbase8(i);
        for (int g = lane; g <= gi; g += 32) {
            float v = __ldg(crow + g);
            int p = pos[g];
            if (p >= 0) Apk[rb + p] = v;
        }
    }
    // residual row n (augmented) + identity pads
    {
        int rbn = rowbase8(n);
        for (int j = tid; j < n; j += NTHREADS)
            Apk[rbn + j] = x[b*DIM + idx[j]] - mu[idx[j]];
        if (tid == 0) Apk[rbn + n] = BIGDIAG;
        for (int i = n + 1 + tid; i < N; i += NTHREADS)
            Apk[rowbase8(i) + i] = 1.f;
    }
    __syncthreads();

    // ================= rank-16 blocked Cholesky =================
    for (int kb = 0; kb < N; kb += 16) {
        // ---- (a) 16x16 diagonal factor (warp 0) ----
        if (tid < 32) factor_diag(Apk, kb, lane, L16, invd);
        __syncthreads();

        const int r0 = kb + 16;
        const int M  = N - r0;
        if (M <= 0) break;

        // ---- (b) panel solve: rows r0..N-1 ----
        for (int i = r0 + tid; i < N; i += NTHREADS) {
            float* rowp = Apk + rowbase8(i) + kb;
            float bb[16];
            {
                float4* rp = (float4*)rowp;
                float4 q0 = rp[0], q1 = rp[1], q2 = rp[2], q3 = rp[3];
                bb[0]=q0.x; bb[1]=q0.y; bb[2]=q0.z; bb[3]=q0.w;
                bb[4]=q1.x; bb[5]=q1.y; bb[6]=q1.z; bb[7]=q1.w;
                bb[8]=q2.x; bb[9]=q2.y; bb[10]=q2.z; bb[11]=q2.w;
                bb[12]=q3.x; bb[13]=q3.y; bb[14]=q3.z; bb[15]=q3.w;
            }
            #pragma unroll
            for (int k = 0; k < 16; k++) {
                float acc = bb[k];
                #pragma unroll
                for (int m = 0; m < k; m++)
                    acc -= bb[m] * L16[k][m];
                bb[k] = acc * invd[k];
            }
            {
                float4* rp = (float4*)rowp;
                rp[0] = make_float4(bb[0], bb[1], bb[2], bb[3]);
                rp[1] = make_float4(bb[4], bb[5], bb[6], bb[7]);
                rp[2] = make_float4(bb[8], bb[9], bb[10], bb[11]);
                rp[3] = make_float4(bb[12], bb[13], bb[14], bb[15]);
            }
        }
        __syncthreads();

        // ---- (c) trailing rank-16 update: warp-cooperative 32x16 tiles,
        //      broadcast u-row loads, fma-neg accumulate, diag by predicate ----
        const int G   = (M + 31) >> 5;
        const int nit = G * (G + 1);
        for (int e = wrp; e < nit; e += NWARPS) {
            int code = eLUT[e];
            int gg = code >> 8, jb = code & 255;
            int i  = r0 + 32 * gg + lane;
            int j0 = r0 + 16 * jb;
            int qi = i >> 3;
            bool vA = (i < N) && (qi >= (j0 >> 3));
            bool vB = (i < N) && (qi >= ((j0 + 8) >> 3));
            int bi  = vA ? rowbase8(i) : 0;
            int wjA = 8 * (j0 >> 3) + 12;
            int bjA = rowbase8(j0);
            int bjB = bjA + 8 * wjA;
            int wjB = wjA + 8;

            float4 z4 = make_float4(0.f, 0.f, 0.f, 0.f);
            float4 cA0 = z4, cA1 = z4, cB0 = z4, cB1 = z4;
            if (vA) {
                cA0 = *(float4*)(Apk + bi + j0);
                cA1 = *(float4*)(Apk + bi + j0 + 4);
            }
            if (vB) {
                cB0 = *(float4*)(Apk + bi + j0 + 8);
                cB1 = *(float4*)(Apk + bi + j0 + 12);
            }
            #pragma unroll
            for (int kc = 0; kc < 16; kc += 4) {
                float4 p = z4;
                if (vA) p = *(const float4*)(Apk + bi + kb + kc);
                const float* uA = Apk + bjA + kb + kc;
                const float* uB = Apk + bjB + kb + kc;
                float4 u;
                u = *(const float4*)(uA         ); DOT4N(cA0.x, p, u);
                u = *(const float4*)(uA + 1*wjA); DOT4N(cA0.y, p, u);
                u = *(const float4*)(uA + 2*wjA); DOT4N(cA0.z, p, u);
                u = *(const float4*)(uA + 3*wjA); DOT4N(cA0.w, p, u);
                u = *(const float4*)(uA + 4*wjA); DOT4N(cA1.x, p, u);
                u = *(const float4*)(uA + 5*wjA); DOT4N(cA1.y, p, u);
                u = *(const float4*)(uA + 6*wjA); DOT4N(cA1.z, p, u);
                u = *(const float4*)(uA + 7*wjA); DOT4N(cA1.w, p, u);
                u = *(const float4*)(uB         ); DOT4N(cB0.x, p, u);
                u = *(const float4*)(uB + 1*wjB); DOT4N(cB0.y, p, u);
                u = *(const float4*)(uB + 2*wjB); DOT4N(cB0.z, p, u);
                u = *(const float4*)(uB + 3*wjB); DOT4N(cB0.w, p, u);
                u = *(const float4*)(uB + 4*wjB); DOT4N(cB1.x, p, u);
                u = *(const float4*)(uB + 5*wjB); DOT4N(cB1.y, p, u);
                u = *(const float4*)(uB + 6*wjB); DOT4N(cB1.z, p, u);
                u = *(const float4*)(uB + 7*wjB); DOT4N(cB1.w, p, u);
            }
            if (vA) {
                *(float4*)(Apk + bi + j0)      = cA0;
                *(float4*)(Apk + bi + j0 + 4)  = cA1;
            }
            if (vB) {
                *(float4*)(Apk + bi + j0 + 8)  = cB0;
                *(float4*)(Apk + bi + j0 + 12) = cB1;
            }
        }
        __syncthreads();
    }

    // ---- reductions: quad from residual row, logdet from diag ----
    float q = 0.f, ls = 0.f;
    {
        int rbn = rowbase8(n);
        for (int j = tid; j < n; j += NTHREADS) {
            float z = Apk[rbn + j];
            q += z * z;
            ls += __logf(Apk[rowbase8(j) + j]);
        }
    }
    #pragma unroll
    for (int off = 16; off > 0; off >>= 1) {
        q  += __shfl_down_sync(0xffffffffu, q,  off);
        ls += __shfl_down_sync(0xffffffffu, ls, off);
    }
    if (lane == 0) { redq[wrp] = q; redl[wrp] = ls; }
    __syncthreads();
    if (wrp == 0) {
        float qq = (lane < NWARPS) ? redq[lane] : 0.f;
        float ll = (lane < NWARPS) ? redl[lane] : 0.f;
        #pragma unroll
        for (int off = 16; off > 0; off >>= 1) {
            qq += __shfl_down_sync(0xffffffffu, qq, off);
            ll += __shfl_down_sync(0xffffffffu, ll, off);
        }
        if (lane == 0)
            out[b] = 0.5f * (qq + 2.f * ll + (float)n * LOG_2PI);
    }
}

// ---------------------------------------------------------------------------
extern "C" void kernel_launch(void* const* d_in, const int* in_sizes, int n_in,
                              void* d_out, int out_size)
{
    const float* x    = (const float*)d_in[0];
    const float* mu   = (const float*)d_in[1];
    const float* ld   = (const float*)d_in[2];
    const float* lt   = (const float*)d_in[3];
    const void*  mask = d_in[4];
    float* out = (float*)d_out;

    build_A_kernel<<<(DIM * DIM + 255) / 256, 256>>>(ld, lt);
    lut_kernel<<<1, 128>>>();
    cov_kernel<<<(DIM / 32) * (DIM / 32 + 1) / 2, 256>>>();

    size_t smem = (size_t)APK_FLOATS * 4 + (size_t)NMAX * 4;
    cudaFuncSetAttribute(mgauss_kernel, cudaFuncAttributeMaxDynamicSharedMemorySize, (int)smem);
    mgauss_kernel<<<BATCH, NTHREADS, smem>>>(x, mu, mask, out);
}

// round 11
// speedup vs baseline: 1.1876x; 1.1876x over previous
#include <cuda_runtime.h>
#include <math.h>

#define DIM 512
#define BATCH 256
#define NMAX 320
#define NTHREADS 512
#define NWARPS (NTHREADS/32)
#define LOG_2PI 1.8378770664093453f
#define BIGDIAG 1e30f
#define APK_FLOATS 53760   /* rowbase8(320) */
#define NITEMS 60          /* 2G^2+2G, G=5 (64-row groups, 16-col j-blocks) */

__device__ float g_A[DIM*DIM];
__device__ float g_cov[DIM*DIM];
__device__ int   g_elut[NITEMS];

// Row-padded packed lower triangle, width(row i) = 8*ceil((i+1)/8) + 4 floats.
// Stride ≡ 4 (mod 8) floats -> conflict-free divergent LDS.128 across rows.
__device__ __forceinline__ int rowbase8(int i) {
    int q = i >> 3, r = i & 7;
    return 32*q*(q+2) + r*(8*q + 12);
}

// ---------------------------------------------------------------------------
__global__ void build_A_kernel(const float* __restrict__ ld,
                               const float* __restrict__ lt)
{
    int t = blockIdx.x * blockDim.x + threadIdx.x;
    if (t >= DIM * DIM) return;
    int i = t / DIM, j = t % DIM;
    float v;
    if (j < i)       v = lt[i * (i - 1) / 2 + j];
    else if (j == i) v = expf(ld[i]);
    else             v = 0.f;
    g_A[t] = v;
}

// ---------------------------------------------------------------------------
// (2nd launch: keeps the launch pattern that makes ncu -s 5 land on mgauss)
__global__ void lut_kernel()
{
    int e = blockIdx.x * blockDim.x + threadIdx.x;
    if (e >= NITEMS) return;
    int g = (int)((sqrtf(2.f * e + 1.f) - 1.f) * 0.5f);
    while (2 * (g + 1) * (g + 2) <= e) g++;
    while (2 * g * (g + 1) > e) g--;
    g_elut[e] = (g << 8) | (e - 2 * g * (g + 1));
}

// ---------------------------------------------------------------------------
__global__ void cov_kernel()
{
    int lb = blockIdx.x;
    int bi = (int)((sqrtf(8.f * lb + 1.f) - 1.f) * 0.5f);
    while ((bi + 1) * (bi + 2) / 2 <= lb) bi++;
    while (bi * (bi + 1) / 2 > lb) bi--;
    int bj = lb - bi * (bi + 1) / 2;

    __shared__ float As[32][33];
    __shared__ float Bs[32][33];

    int tx = threadIdx.x & 31;
    int ty = threadIdx.x >> 5;
    float acc[4] = {0.f, 0.f, 0.f, 0.f};

    int kmax = (bj + 1) * 32;
    for (int kt = 0; kt < kmax; kt += 32) {
        #pragma unroll
        for (int rr = 0; rr < 4; rr++) {
            int r = ty + rr * 8;
            As[r][tx] = g_A[(bi * 32 + r) * DIM + kt + tx];
            Bs[r][tx] = g_A[(bj * 32 + r) * DIM + kt + tx];
        }
        __syncthreads();
        #pragma unroll
        for (int k = 0; k < 32; k++) {
            float bv = Bs[tx][k];
            #pragma unroll
            for (int rr = 0; rr < 4; rr++)
                acc[rr] += As[ty + rr * 8][k] * bv;
        }
        __syncthreads();
    }
    #pragma unroll
    for (int rr = 0; rr < 4; rr++) {
        int r = ty + rr * 8;
        g_cov[(bi * 32 + r) * DIM + bj * 32 + tx] = acc[rr];
    }
}

// negate-accumulate: 4 pure FFMA (neg is a free source modifier), no FMUL/FADD
#define DOT4N(cc, p, u) \
    cc = fmaf(-(p).x, (u).x, fmaf(-(p).y, (u).y, fmaf(-(p).z, (u).z, fmaf(-(p).w, (u).w, cc))))

// 16x16 diagonal block Cholesky by one warp in registers (lanes 0..15 = rows).
__device__ __forceinline__ void factor_diag(float* Apk, int kb, int lane,
                                            float (*L16)[16], float* invd)
{
    const int l = lane;
    float a[16];
    {
        int row = kb + (l < 16 ? l : 0);
        const float4* rp = (const float4*)(Apk + rowbase8(row) + kb);
        float4 q0 = rp[0], q1 = rp[1], q2 = rp[2], q3 = rp[3];
        a[0]=q0.x; a[1]=q0.y; a[2]=q0.z; a[3]=q0.w;
        a[4]=q1.x; a[5]=q1.y; a[6]=q1.z; a[7]=q1.w;
        a[8]=q2.x; a[9]=q2.y; a[10]=q2.z; a[11]=q2.w;
        a[12]=q3.x; a[13]=q3.y; a[14]=q3.z; a[15]=q3.w;
    }
    #pragma unroll
    for (int k = 0; k < 16; k++) {
        float dk = __shfl_sync(0xffffffffu, a[k], k);
        float s  = sqrtf(dk);
        float iv = 1.f / s;
        if (l == k) { a[k] = s; invd[k] = iv; }
        else if (l > k && l < 16) a[k] *= iv;
        #pragma unroll
        for (int j = k + 1; j < 16; j++) {
            float ajk = __shfl_sync(0xffffffffu, a[k], j);
            if (l >= j && l < 16) a[j] -= a[k] * ajk;
        }
    }
    if (l < 16) {
        int rb = rowbase8(kb + l) + kb;
        #pragma unroll
        for (int k = 0; k < 16; k++) {
            L16[l][k] = a[k];
            if (k <= l) Apk[rb + k] = a[k];
        }
    }
}

// ---------------------------------------------------------------------------
__global__ __launch_bounds__(NTHREADS)
void mgauss_kernel(const float* __restrict__ x,
                   const float* __restrict__ mu,
                   const void*  __restrict__ mask,
                   float* __restrict__ out)
{
    extern __shared__ float sm[];
    float* Apk = sm;                            // APK_FLOATS
    int*   idx = (int*)(sm + APK_FLOATS);       // NMAX ints

    __shared__ float L16[16][16];
    __shared__ float invd[16];
    __shared__ int   pos[DIM];
    __shared__ float red[2*NTHREADS];
    __shared__ unsigned cbal[16];
    __shared__ int   ccnt[17];
    __shared__ int   s_n, s_isint;
    __shared__ int   eLUT[NITEMS];

    const int tid  = threadIdx.x;
    const int lane = tid & 31;
    const int wrp  = tid >> 5;
    const int b    = blockIdx.x;

    // ---- item LUT: e -> (64-row group g, 16-col block jb); cum(g)=2g(g+1) ----
    for (int e = tid; e < NITEMS; e += NTHREADS) {
        int g = (int)((sqrtf(2.f * e + 1.f) - 1.f) * 0.5f);
        while (2 * (g + 1) * (g + 2) <= e) g++;
        while (2 * g * (g + 1) > e) g--;
        eLUT[e] = (g << 8) | (e - 2 * g * (g + 1));
    }

    // ---- mask dtype detect ----
    if (tid == 0) {
        const unsigned char* mb = (const unsigned char*)mask;
        int isint = 1;
        for (int k = 0; k < 100; k++)
            if (mb[4*k+1] | mb[4*k+2] | mb[4*k+3]) { isint = 0; break; }
        s_isint = isint;
    }
    __syncthreads();
    const int is_int = s_isint;

    // ---- index list via ballot + prefix ----
    if (wrp < 16) {
        int gi = wrp * 32 + lane;
        int mv;
        if (is_int) mv = (((const int*)mask)[b*DIM + gi] != 0);
        else        mv = (((const unsigned char*)mask)[b*DIM + gi] != 0);
        unsigned bal = __ballot_sync(0xffffffffu, mv);
        if (lane == 0) { cbal[wrp] = bal; ccnt[wrp+1] = __popc(bal); }
    }
    __syncthreads();
    if (tid == 0) {
        ccnt[0] = 0;
        for (int c = 1; c <= 16; c++) ccnt[c] += ccnt[c-1];
        int n = ccnt[16];
        if (n > NMAX - 1) n = NMAX - 1;
        s_n = n;
    }
    __syncthreads();
    const int n = s_n;
    if (wrp < 16) {
        unsigned bal = cbal[wrp];
        if ((bal >> lane) & 1u) {
            int p = ccnt[wrp] + __popc(bal & ((1u << lane) - 1u));
            if (p < n) idx[p] = wrp * 32 + lane;
        }
    }
    const int N = (n + 1 + 15) & ~15;           // includes residual row n

    // ---- zero Apk, inverse map ----
    {
        float4 z4 = make_float4(0.f, 0.f, 0.f, 0.f);
        for (int t = tid; t < (APK_FLOATS >> 2); t += NTHREADS)
            ((float4*)Apk)[t] = z4;
        for (int g = tid; g < DIM; g += NTHREADS) pos[g] = -1;
    }
    __syncthreads();
    for (int p = tid; p < n; p += NTHREADS) pos[idx[p]] = p;
    __syncthreads();

    // ---- gather cov rows (coalesced) + scatter into packed smem ----
    for (int i = wrp; i < n; i += NWARPS) {
        int gi = idx[i];
        const float* crow = g_cov + gi * DIM;
        int rb = rowbase8(i);
        for (int g = lane; g <= gi; g += 32) {
            float v = __ldg(crow + g);
            int p = pos[g];
            if (p >= 0) Apk[rb + p] = v;
        }
    }
    // residual row n (augmented) + identity pads
    {
        int rbn = rowbase8(n);
        for (int j = tid; j < n; j += NTHREADS)
            Apk[rbn + j] = x[b*DIM + idx[j]] - mu[idx[j]];
        if (tid == 0) Apk[rbn + n] = BIGDIAG;
        for (int i = n + 1 + tid; i < N; i += NTHREADS)
            Apk[rowbase8(i) + i] = 1.f;
    }
    __syncthreads();

    // ================= rank-16 blocked Cholesky =================
    for (int kb = 0; kb < N; kb += 16) {
        // ---- (a) 16x16 diagonal factor (warp 0) ----
        if (tid < 32) factor_diag(Apk, kb, lane, L16, invd);
        __syncthreads();

        const int r0 = kb + 16;
        const int M  = N - r0;
        if (M <= 0) break;

        // ---- (b) panel solve: rows r0..N-1 ----
        for (int i = r0 + tid; i < N; i += NTHREADS) {
            float* rowp = Apk + rowbase8(i) + kb;
            float bb[16];
            {
                float4* rp = (float4*)rowp;
                float4 q0 = rp[0], q1 = rp[1], q2 = rp[2], q3 = rp[3];
                bb[0]=q0.x; bb[1]=q0.y; bb[2]=q0.z; bb[3]=q0.w;
                bb[4]=q1.x; bb[5]=q1.y; bb[6]=q1.z; bb[7]=q1.w;
                bb[8]=q2.x; bb[9]=q2.y; bb[10]=q2.z; bb[11]=q2.w;
                bb[12]=q3.x; bb[13]=q3.y; bb[14]=q3.z; bb[15]=q3.w;
            }
            #pragma unroll
            for (int k = 0; k < 16; k++) {
                float acc = bb[k];
                #pragma unroll
                for (int m = 0; m < k; m++)
                    acc -= bb[m] * L16[k][m];
                bb[k] = acc * invd[k];
            }
            {
                float4* rp = (float4*)rowp;
                rp[0] = make_float4(bb[0], bb[1], bb[2], bb[3]);
                rp[1] = make_float4(bb[4], bb[5], bb[6], bb[7]);
                rp[2] = make_float4(bb[8], bb[9], bb[10], bb[11]);
                rp[3] = make_float4(bb[12], bb[13], bb[14], bb[15]);
            }
        }
        __syncthreads();

        // ---- (c) trailing rank-16 update: warp-cooperative 64x16 tiles,
        //      two rows per lane share 16 broadcast u-rows ----
        const int G   = (M + 63) >> 6;
        const int nit = 2 * G * (G + 1);
        for (int e = wrp; e < nit; e += NWARPS) {
            int code = eLUT[e];
            int gg = code >> 8, jb = code & 255;
            int j0 = r0 + 16 * jb;
            if (j0 >= N) continue;   // phantom tile: no valid writes; guard u reads
            int i0 = r0 + 64 * gg + lane;
            int i1 = i0 + 32;
            int q0i = i0 >> 3, q1i = i1 >> 3;
            int jq0 = j0 >> 3, jq1 = (j0 + 8) >> 3;
            bool vA0 = (i0 < N) && (q0i >= jq0);
            bool vB0 = (i0 < N) && (q0i >= jq1);
            bool vA1 = (i1 < N) && (q1i >= jq0);
            bool vB1 = (i1 < N) && (q1i >= jq1);
            int bi0 = vA0 ? rowbase8(i0) : 0;
            int bi1 = vA1 ? rowbase8(i1) : 0;
            int wjA = 8 * jq0 + 12;
            int bjA = rowbase8(j0);
            int bjB = bjA + 8 * wjA;
            int wjB = wjA + 8;

            float4 z4 = make_float4(0.f, 0.f, 0.f, 0.f);
            float4 cA0 = z4, cA1 = z4, cB0 = z4, cB1 = z4;   // row i0
            float4 dA0 = z4, dA1 = z4, dB0 = z4, dB1 = z4;   // row i1
            if (vA0) {
                cA0 = *(float4*)(Apk + bi0 + j0);
                cA1 = *(float4*)(Apk + bi0 + j0 + 4);
            }
            if (vB0) {
                cB0 = *(float4*)(Apk + bi0 + j0 + 8);
                cB1 = *(float4*)(Apk + bi0 + j0 + 12);
            }
            if (vA1) {
                dA0 = *(float4*)(Apk + bi1 + j0);
                dA1 = *(float4*)(Apk + bi1 + j0 + 4);
            }
            if (vB1) {
                dB0 = *(float4*)(Apk + bi1 + j0 + 8);
                dB1 = *(float4*)(Apk + bi1 + j0 + 12);
            }
            #pragma unroll
            for (int kc = 0; kc < 16; kc += 4) {
                float4 p0 = z4, p1 = z4;
                if (vA0) p0 = *(const float4*)(Apk + bi0 + kb + kc);
                if (vA1) p1 = *(const float4*)(Apk + bi1 + kb + kc);
                const float* uA = Apk + bjA + kb + kc;
                const float* uB = Apk + bjB + kb + kc;
                float4 u;
                u = *(const float4*)(uA         ); DOT4N(cA0.x, p0, u); DOT4N(dA0.x, p1, u);
                u = *(const float4*)(uA + 1*wjA); DOT4N(cA0.y, p0, u); DOT4N(dA0.y, p1, u);
                u = *(const float4*)(uA + 2*wjA); DOT4N(cA0.z, p0, u); DOT4N(dA0.z, p1, u);
                u = *(const float4*)(uA + 3*wjA); DOT4N(cA0.w, p0, u); DOT4N(dA0.w, p1, u);
                u = *(const float4*)(uA + 4*wjA); DOT4N(cA1.x, p0, u); DOT4N(dA1.x, p1, u);
                u = *(const float4*)(uA + 5*wjA); DOT4N(cA1.y, p0, u); DOT4N(dA1.y, p1, u);
                u = *(const float4*)(uA + 6*wjA); DOT4N(cA1.z, p0, u); DOT4N(dA1.z, p1, u);
                u = *(const float4*)(uA + 7*wjA); DOT4N(cA1.w, p0, u); DOT4N(dA1.w, p1, u);
                u = *(const float4*)(uB         ); DOT4N(cB0.x, p0, u); DOT4N(dB0.x, p1, u);
                u = *(const float4*)(uB + 1*wjB); DOT4N(cB0.y, p0, u); DOT4N(dB0.y, p1, u);
                u = *(const float4*)(uB + 2*wjB); DOT4N(cB0.z, p0, u); DOT4N(dB0.z, p1, u);
                u = *(const float4*)(uB + 3*wjB); DOT4N(cB0.w, p0, u); DOT4N(dB0.w, p1, u);
                u = *(const float4*)(uB + 4*wjB); DOT4N(cB1.x, p0, u); DOT4N(dB1.x, p1, u);
                u = *(const float4*)(uB + 5*wjB); DOT4N(cB1.y, p0, u); DOT4N(dB1.y, p1, u);
                u = *(const float4*)(uB + 6*wjB); DOT4N(cB1.z, p0, u); DOT4N(dB1.z, p1, u);
                u = *(const float4*)(uB + 7*wjB); DOT4N(cB1.w, p0, u); DOT4N(dB1.w, p1, u);
            }
            if (vA0) {
                *(float4*)(Apk + bi0 + j0)      = cA0;
                *(float4*)(Apk + bi0 + j0 + 4)  = cA1;
            }
            if (vB0) {
                *(float4*)(Apk + bi0 + j0 + 8)  = cB0;
                *(float4*)(Apk + bi0 + j0 + 12) = cB1;
            }
            if (vA1) {
                *(float4*)(Apk + bi1 + j0)      = dA0;
                *(float4*)(Apk + bi1 + j0 + 4)  = dA1;
            }
            if (vB1) {
                *(float4*)(Apk + bi1 + j0 + 8)  = dB0;
                *(float4*)(Apk + bi1 + j0 + 12) = dB1;
            }
        }
        __syncthreads();
    }

    // ---- reductions: quad from residual row, logdet from diag ----
    float q = 0.f, ls = 0.f;
    {
        int rbn = rowbase8(n);
        for (int j = tid; j < n; j += NTHREADS) {
            float z = Apk[rbn + j];
            q += z * z;
            ls += __logf(Apk[rowbase8(j) + j]);
        }
    }
    red[tid] = q;
    red[NTHREADS + tid] = ls;
    __syncthreads();
    for (int s = NTHREADS / 2; s > 0; s >>= 1) {
        if (tid < s) {
            red[tid] += red[tid + s];
            red[NTHREADS + tid] += red[NTHREADS + tid + s];
        }
        __syncthreads();
    }
    if (tid == 0)
        out[b] = 0.5f * (red[0] + 2.f * red[NTHREADS] + (float)n * LOG_2PI);
}

// ---------------------------------------------------------------------------
extern "C" void kernel_launch(void* const* d_in, const int* in_sizes, int n_in,
                              void* d_out, int out_size)
{
    const float* x    = (const float*)d_in[0];
    const float* mu   = (const float*)d_in[1];
    const float* ld   = (const float*)d_in[2];
    const float* lt   = (const float*)d_in[3];
    const void*  mask = d_in[4];
    float* out = (float*)d_out;

    build_A_kernel<<<(DIM * DIM + 255) / 256, 256>>>(ld, lt);
    lut_kernel<<<1, 128>>>();
    cov_kernel<<<(DIM / 32) * (DIM / 32 + 1) / 2, 256>>>();

    size_t smem = (size_t)APK_FLOATS * 4 + (size_t)NMAX * 4;
    cudaFuncSetAttribute(mgauss_kernel, cudaFuncAttributeMaxDynamicSharedMemorySize, (int)smem);
    mgauss_kernel<<<BATCH, NTHREADS, smem>>>(x, mu, mask, out);
}